// round 1
// baseline (speedup 1.0000x reference)
#include <cuda_runtime.h>
#include <math.h>

#define TPB 256
#define RT  16            // rows per CTA

#define D_IN   480
#define NM0    128
#define NM1    64
#define NM2    32
#define NH0    512
#define NH1    256
#define NH2    128
#define W0COLS 896        // H0 + G

#define EPSF    1e-8f
#define INV_S0  0.08838834764831845f   // 1/sqrt(128)
#define INV_S1  0.125f                 // 1/sqrt(64)
#define INV_S2  0.17677669529663687f   // 1/sqrt(32)
#define INV_T0  0.04419417382415922f   // 1/sqrt(512)
#define INV_T1  0.0625f                // 1/sqrt(256)
#define INV_T2  0.08838834764831845f   // 1/sqrt(128)

// All [col][row] arrays use RT=16 row-minor so GEMM loops read 4x float4 broadcasts.
struct Smem {
    float y0[NM0 * RT];           //  8 KB  y0 * (1/S0)
    float y1[3 * NM1 * RT];       // 12 KB  [(m*64+u)][r], * (1/S1)
    float y2[5 * NM2 * RT];       // 10 KB  [(m*32+u)][r], * (1/S2)
    float s [NH0 * RT];           // 32 KB  silu(h0[:512]) * (1/T0)
    float g [(NH1 + NH2) * RT];   // 24 KB  sigmoid(h0[512:])
    float z1[3 * NH1 * RT];       // 48 KB  [(m*256+w)][r], * (1/T1)
    float z2[5 * NH2 * RT];       // 40 KB  [(m*128+w)][r], * (1/T2)
    float o0[RT * NM0];           //  8 KB  r-major
    float o1[RT * 3 * NM1];       // 12 KB  r-major: [r][m*64+v]
    float o2[RT * 5 * NM2];       // 10 KB  r-major: [r][m*32+v]
    float scratch[RT * NM0];      //  8 KB  o0 K-split partial, r-major
};                                // total ~212 KB

__global__ __launch_bounds__(TPB, 1)
void ffn_kernel(const float* __restrict__ x,
                const float* __restrict__ nw0, const float* __restrict__ nb0,
                const float* __restrict__ nw1, const float* __restrict__ nw2,
                const float* __restrict__ W0,  const float* __restrict__ b0,
                const float* __restrict__ W1,  const float* __restrict__ W2,
                const float* __restrict__ V0,  const float* __restrict__ c0,
                const float* __restrict__ V1,  const float* __restrict__ V2,
                const float* __restrict__ alpha,
                float* __restrict__ out)
{
    extern __shared__ float smem_raw[];
    Smem& sm = *reinterpret_cast<Smem*>(smem_raw);
    const int tid  = threadIdx.x;
    const int row0 = blockIdx.x * RT;

    // ================= Stage 1: norms (1 warp -> 2 rows) =================
    {
        const int warp = tid >> 5, lane = tid & 31;
        #pragma unroll
        for (int rr = 0; rr < 2; ++rr) {
            const int r = warp * 2 + rr;
            const float* xr = x + (size_t)(row0 + r) * D_IN;
            float vals[15];
            float sum0 = 0.f, sq0 = 0.f, sq12 = 0.f;
            #pragma unroll
            for (int k = 0; k < 15; ++k) {
                const int c = lane + 32 * k;
                const float v = xr[c];
                vals[k] = v;
                if (k < 4)       { sum0 += v; sq0 += v * v; }
                else if (k < 10) { sq12 += v * v * (0.5f / 192.0f); }
                else             { sq12 += v * v * (0.5f / 160.0f); }
            }
            #pragma unroll
            for (int o = 16; o > 0; o >>= 1) {
                sum0 += __shfl_xor_sync(0xffffffffu, sum0, o);
                sq0  += __shfl_xor_sync(0xffffffffu, sq0,  o);
                sq12 += __shfl_xor_sync(0xffffffffu, sq12, o);
            }
            const float mu    = sum0 * (1.0f / 128.0f);
            const float var   = sq0 * (1.0f / 128.0f) - mu * mu;
            const float is0   = rsqrtf(var + EPSF);
            const float inv12 = rsqrtf(sq12 + EPSF);
            #pragma unroll
            for (int k = 0; k < 15; ++k) {
                const int c = lane + 32 * k;
                const float v = vals[k];
                if (k < 4) {
                    sm.y0[c * RT + r] = ((v - mu) * is0 * nw0[c] + nb0[c]) * INV_S0;
                } else if (k < 10) {
                    const int cc = c - 128; const int u = cc / 3; const int m = cc - 3 * u;
                    sm.y1[(m * NM1 + u) * RT + r] = v * inv12 * nw1[u] * INV_S1;
                } else {
                    const int cc = c - 320; const int u = cc / 5; const int m = cc - 5 * u;
                    sm.y2[(m * NM2 + u) * RT + r] = v * inv12 * nw2[u] * INV_S2;
                }
            }
        }
    }
    __syncthreads();

    // ================= Stage 2a: H0 = Y0 @ W0 (+b0), activations ===========
    if (tid < 224) {
        const int j0 = tid * 4;
        float acc[4][RT];
        #pragma unroll
        for (int c = 0; c < 4; ++c)
            #pragma unroll
            for (int r = 0; r < RT; ++r) acc[c][r] = 0.f;

        float4 w = *(const float4*)(W0 + j0);
        for (int u = 0; u < NM0; ++u) {
            const int un = (u < NM0 - 1) ? u + 1 : u;
            const float4 wn = *(const float4*)(W0 + un * W0COLS + j0);
            const float4* yp = (const float4*)(sm.y0 + u * RT);
            float yv[RT];
            ((float4*)yv)[0] = yp[0]; ((float4*)yv)[1] = yp[1];
            ((float4*)yv)[2] = yp[2]; ((float4*)yv)[3] = yp[3];
            #pragma unroll
            for (int r = 0; r < RT; ++r) {
                acc[0][r] = fmaf(yv[r], w.x, acc[0][r]);
                acc[1][r] = fmaf(yv[r], w.y, acc[1][r]);
                acc[2][r] = fmaf(yv[r], w.z, acc[2][r]);
                acc[3][r] = fmaf(yv[r], w.w, acc[3][r]);
            }
            w = wn;
        }
        #pragma unroll
        for (int c = 0; c < 4; ++c) {
            const int col = j0 + c;
            const float bb = b0[col];
            if (col < NH0) {
                #pragma unroll
                for (int rq = 0; rq < 4; ++rq) {
                    float4 o;
                    float h;
                    h = acc[c][4*rq+0] + bb; o.x = h / (1.0f + expf(-h)) * INV_T0;
                    h = acc[c][4*rq+1] + bb; o.y = h / (1.0f + expf(-h)) * INV_T0;
                    h = acc[c][4*rq+2] + bb; o.z = h / (1.0f + expf(-h)) * INV_T0;
                    h = acc[c][4*rq+3] + bb; o.w = h / (1.0f + expf(-h)) * INV_T0;
                    ((float4*)(sm.s + col * RT))[rq] = o;
                }
            } else {
                #pragma unroll
                for (int rq = 0; rq < 4; ++rq) {
                    float4 o;
                    o.x = 1.0f / (1.0f + expf(-(acc[c][4*rq+0] + bb)));
                    o.y = 1.0f / (1.0f + expf(-(acc[c][4*rq+1] + bb)));
                    o.z = 1.0f / (1.0f + expf(-(acc[c][4*rq+2] + bb)));
                    o.w = 1.0f / (1.0f + expf(-(acc[c][4*rq+3] + bb)));
                    ((float4*)(sm.g + (col - NH0) * RT))[rq] = o;
                }
            }
        }
    }
    __syncthreads();

    // ================= Stage 2b: h1 -> z1 (3 heads) ========================
    if (tid < 192) {
        const int m  = tid >> 6;
        const int j0 = (tid & 63) * 4;
        float acc[4][RT];
        #pragma unroll
        for (int c = 0; c < 4; ++c)
            #pragma unroll
            for (int r = 0; r < RT; ++r) acc[c][r] = 0.f;

        const float* yb = sm.y1 + (m * NM1) * RT;
        float4 w = *(const float4*)(W1 + j0);
        for (int u = 0; u < NM1; ++u) {
            const int un = (u < NM1 - 1) ? u + 1 : u;
            const float4 wn = *(const float4*)(W1 + un * NH1 + j0);
            const float4* yp = (const float4*)(yb + u * RT);
            float yv[RT];
            ((float4*)yv)[0] = yp[0]; ((float4*)yv)[1] = yp[1];
            ((float4*)yv)[2] = yp[2]; ((float4*)yv)[3] = yp[3];
            #pragma unroll
            for (int r = 0; r < RT; ++r) {
                acc[0][r] = fmaf(yv[r], w.x, acc[0][r]);
                acc[1][r] = fmaf(yv[r], w.y, acc[1][r]);
                acc[2][r] = fmaf(yv[r], w.z, acc[2][r]);
                acc[3][r] = fmaf(yv[r], w.w, acc[3][r]);
            }
            w = wn;
        }
        #pragma unroll
        for (int c = 0; c < 4; ++c) {
            const int col = j0 + c;
            #pragma unroll
            for (int rq = 0; rq < 4; ++rq) {
                const float4 g4 = ((const float4*)(sm.g + col * RT))[rq];
                float4 o;
                o.x = acc[c][4*rq+0] * g4.x * INV_T1;
                o.y = acc[c][4*rq+1] * g4.y * INV_T1;
                o.z = acc[c][4*rq+2] * g4.z * INV_T1;
                o.w = acc[c][4*rq+3] * g4.w * INV_T1;
                ((float4*)(sm.z1 + (m * NH1 + col) * RT))[rq] = o;
            }
        }
    }

    // ================= Stage 2c: h2 -> z2 (5 heads) ========================
    if (tid >= 96) {
        const int t  = tid - 96;
        const int m  = t >> 5;
        const int j0 = (t & 31) * 4;
        float acc[4][RT];
        #pragma unroll
        for (int c = 0; c < 4; ++c)
            #pragma unroll
            for (int r = 0; r < RT; ++r) acc[c][r] = 0.f;

        const float* yb = sm.y2 + (m * NM2) * RT;
        float4 w = *(const float4*)(W2 + j0);
        for (int u = 0; u < NM2; ++u) {
            const int un = (u < NM2 - 1) ? u + 1 : u;
            const float4 wn = *(const float4*)(W2 + un * NH2 + j0);
            const float4* yp = (const float4*)(yb + u * RT);
            float yv[RT];
            ((float4*)yv)[0] = yp[0]; ((float4*)yv)[1] = yp[1];
            ((float4*)yv)[2] = yp[2]; ((float4*)yv)[3] = yp[3];
            #pragma unroll
            for (int r = 0; r < RT; ++r) {
                acc[0][r] = fmaf(yv[r], w.x, acc[0][r]);
                acc[1][r] = fmaf(yv[r], w.y, acc[1][r]);
                acc[2][r] = fmaf(yv[r], w.z, acc[2][r]);
                acc[3][r] = fmaf(yv[r], w.w, acc[3][r]);
            }
            w = wn;
        }
        #pragma unroll
        for (int c = 0; c < 4; ++c) {
            const int col = j0 + c;
            #pragma unroll
            for (int rq = 0; rq < 4; ++rq) {
                const float4 g4 = ((const float4*)(sm.g + (NH1 + col) * RT))[rq];
                float4 o;
                o.x = acc[c][4*rq+0] * g4.x * INV_T2;
                o.y = acc[c][4*rq+1] * g4.y * INV_T2;
                o.z = acc[c][4*rq+2] * g4.z * INV_T2;
                o.w = acc[c][4*rq+3] * g4.w * INV_T2;
                ((float4*)(sm.z2 + (m * NH2 + col) * RT))[rq] = o;
            }
        }
    }
    __syncthreads();

    // ================= Stage 4a: o0 = s @ V0 (+c0), K-split by 2 ===========
    float acc0[RT];
    {
        const int j  = tid & 127;
        const int kh = tid >> 7;
        #pragma unroll
        for (int r = 0; r < RT; ++r) acc0[r] = 0.f;
        const int ub = kh * 256;
        for (int uu = 0; uu < 256; uu += 4) {
            const float w0_ = V0[(ub + uu + 0) * NM0 + j];
            const float w1_ = V0[(ub + uu + 1) * NM0 + j];
            const float w2_ = V0[(ub + uu + 2) * NM0 + j];
            const float w3_ = V0[(ub + uu + 3) * NM0 + j];
            #pragma unroll
            for (int q = 0; q < 4; ++q) {
                const float wq = (q == 0) ? w0_ : (q == 1) ? w1_ : (q == 2) ? w2_ : w3_;
                const float4* sp = (const float4*)(sm.s + (ub + uu + q) * RT);
                float yv[RT];
                ((float4*)yv)[0] = sp[0]; ((float4*)yv)[1] = sp[1];
                ((float4*)yv)[2] = sp[2]; ((float4*)yv)[3] = sp[3];
                #pragma unroll
                for (int r = 0; r < RT; ++r) acc0[r] = fmaf(yv[r], wq, acc0[r]);
            }
        }
        if (kh) {
            #pragma unroll
            for (int r = 0; r < RT; ++r) sm.scratch[r * NM0 + j] = acc0[r];
        }
    }
    __syncthreads();
    if (tid < 128) {
        const float cc = c0[tid];
        #pragma unroll
        for (int r = 0; r < RT; ++r)
            sm.o0[r * NM0 + tid] = acc0[r] + sm.scratch[r * NM0 + tid] + cc;
    }

    // ================= Stage 4b: o1 = z1 @ V1 ==============================
    if (tid < 192) {
        const int m = tid >> 6;
        const int j = tid & 63;
        float acc[RT];
        #pragma unroll
        for (int r = 0; r < RT; ++r) acc[r] = 0.f;
        const float* zb = sm.z1 + (m * NH1) * RT;
        for (int u = 0; u < NH1; u += 4) {
            const float w0_ = V1[(u + 0) * NM1 + j];
            const float w1_ = V1[(u + 1) * NM1 + j];
            const float w2_ = V1[(u + 2) * NM1 + j];
            const float w3_ = V1[(u + 3) * NM1 + j];
            #pragma unroll
            for (int q = 0; q < 4; ++q) {
                const float wq = (q == 0) ? w0_ : (q == 1) ? w1_ : (q == 2) ? w2_ : w3_;
                const float4* sp = (const float4*)(zb + (u + q) * RT);
                float yv[RT];
                ((float4*)yv)[0] = sp[0]; ((float4*)yv)[1] = sp[1];
                ((float4*)yv)[2] = sp[2]; ((float4*)yv)[3] = sp[3];
                #pragma unroll
                for (int r = 0; r < RT; ++r) acc[r] = fmaf(yv[r], wq, acc[r]);
            }
        }
        #pragma unroll
        for (int r = 0; r < RT; ++r) sm.o1[r * (3 * NM1) + m * NM1 + j] = acc[r];
    }

    // ================= Stage 4c: o2 = z2 @ V2 ==============================
    if (tid >= 96) {
        const int t = tid - 96;
        const int m = t >> 5;
        const int j = t & 31;
        float acc[RT];
        #pragma unroll
        for (int r = 0; r < RT; ++r) acc[r] = 0.f;
        const float* zb = sm.z2 + (m * NH2) * RT;
        for (int u = 0; u < NH2; u += 4) {
            const float w0_ = V2[(u + 0) * NM2 + j];
            const float w1_ = V2[(u + 1) * NM2 + j];
            const float w2_ = V2[(u + 2) * NM2 + j];
            const float w3_ = V2[(u + 3) * NM2 + j];
            #pragma unroll
            for (int q = 0; q < 4; ++q) {
                const float wq = (q == 0) ? w0_ : (q == 1) ? w1_ : (q == 2) ? w2_ : w3_;
                const float4* sp = (const float4*)(zb + (u + q) * RT);
                float yv[RT];
                ((float4*)yv)[0] = sp[0]; ((float4*)yv)[1] = sp[1];
                ((float4*)yv)[2] = sp[2]; ((float4*)yv)[3] = sp[3];
                #pragma unroll
                for (int r = 0; r < RT; ++r) acc[r] = fmaf(yv[r], wq, acc[r]);
            }
        }
        #pragma unroll
        for (int r = 0; r < RT; ++r) sm.o2[r * (5 * NM2) + m * NM2 + j] = acc[r];
    }
    __syncthreads();

    // ================= Stage 5: out = x + tanh(alpha) * dx =================
    {
        const float t = tanhf(alpha[0]);
        for (int i = tid; i < RT * D_IN; i += TPB) {
            const int r = i / D_IN;
            const int c = i - r * D_IN;
            float dx;
            if (c < 128) {
                dx = sm.o0[r * NM0 + c];
            } else if (c < 320) {
                const int cc = c - 128; const int u = cc / 3; const int m = cc - 3 * u;
                dx = sm.o1[r * (3 * NM1) + m * NM1 + u];
            } else {
                const int cc = c - 320; const int u = cc / 5; const int m = cc - 5 * u;
                dx = sm.o2[r * (5 * NM2) + m * NM2 + u];
            }
            const size_t idx = (size_t)(row0 + r) * D_IN + c;
            out[idx] = x[idx] + t * dx;
        }
    }
}

extern "C" void kernel_launch(void* const* d_in, const int* in_sizes, int n_in,
                              void* d_out, int out_size) {
    const float* x     = (const float*)d_in[0];
    const float* nw0   = (const float*)d_in[1];
    const float* nb0   = (const float*)d_in[2];
    const float* nw1   = (const float*)d_in[3];
    const float* nw2   = (const float*)d_in[4];
    const float* W0    = (const float*)d_in[5];
    const float* b0    = (const float*)d_in[6];
    const float* W1    = (const float*)d_in[7];
    const float* W2    = (const float*)d_in[8];
    const float* V0    = (const float*)d_in[9];
    const float* c0    = (const float*)d_in[10];
    const float* V1    = (const float*)d_in[11];
    const float* V2    = (const float*)d_in[12];
    const float* alpha = (const float*)d_in[13];
    float* out = (float*)d_out;

    const int n = in_sizes[0] / D_IN;
    const int grid = n / RT;

    cudaFuncSetAttribute(ffn_kernel, cudaFuncAttributeMaxDynamicSharedMemorySize,
                         (int)sizeof(Smem));
    ffn_kernel<<<grid, TPB, sizeof(Smem)>>>(x, nw0, nb0, nw1, nw2, W0, b0, W1, W2,
                                            V0, c0, V1, V2, alpha, out);
}

// round 2
// speedup vs baseline: 1.6265x; 1.6265x over previous
#include <cuda_runtime.h>
#include <math.h>

#define TPB 256
#define RT  8             // rows per CTA
#define RP  4             // row pairs (RT/2)

#define D_IN   480
#define NM0    128
#define NM1    64
#define NM2    32
#define NH0    512
#define NH1    256
#define NH2    128
#define W0COLS 896        // H0 + G

#define EPSF    1e-8f
#define INV_S0  0.08838834764831845f   // 1/sqrt(128)
#define INV_S1  0.125f                 // 1/sqrt(64)
#define INV_S2  0.17677669529663687f   // 1/sqrt(32)
#define INV_T0  0.04419417382415922f   // 1/sqrt(512)
#define INV_T1  0.0625f                // 1/sqrt(256)
#define INV_T2  0.08838834764831845f   // 1/sqrt(128)

typedef unsigned long long u64t;

// ---- packed f32x2 helpers (Blackwell FFMA2 path; rt beats scalar FFMA 2x) ----
__device__ __forceinline__ u64t pk2(float v) {
    u64t r; asm("mov.b64 %0, {%1, %1};" : "=l"(r) : "f"(v)); return r;
}
__device__ __forceinline__ void fm2(u64t& d, u64t a, u64t b) {
    asm("fma.rn.f32x2 %0, %1, %2, %0;" : "+l"(d) : "l"(a), "l"(b));
}
__device__ __forceinline__ u64t ml2(u64t a, u64t b) {
    u64t r; asm("mul.rn.f32x2 %0, %1, %2;" : "=l"(r) : "l"(a), "l"(b)); return r;
}
__device__ __forceinline__ float2 up2(u64t v) {
    float2 f; asm("mov.b64 {%0, %1}, %2;" : "=f"(f.x), "=f"(f.y) : "l"(v)); return f;
}

// All [col][row] arrays use RT=8 row-minor: one col = 4 contiguous f32x2 pairs.
struct Smem {
    float y0[NM0 * RT];           //  4 KB
    float y1[3 * NM1 * RT];       //  6 KB
    float y2[5 * NM2 * RT];       //  5 KB
    float s [NH0 * RT];           // 16 KB  silu(h0[:512]) * (1/T0)
    float g [(NH1 + NH2) * RT];   // 12 KB  sigmoid(h0[512:])
    float z1[3 * NH1 * RT];       // 24 KB
    float z2[5 * NH2 * RT];       // 20 KB
    float o0[RT * NM0];           //  4 KB  r-major
    float o1[RT * 3 * NM1];       //  6 KB  r-major
    float o2[RT * 5 * NM2];       //  5 KB  r-major
    float scratch[RT * NM0];      //  4 KB
};                                // ~106 KB -> 2 CTAs/SM

__global__ __launch_bounds__(TPB, 2)
void ffn_kernel(const float* __restrict__ x,
                const float* __restrict__ nw0, const float* __restrict__ nb0,
                const float* __restrict__ nw1, const float* __restrict__ nw2,
                const float* __restrict__ W0,  const float* __restrict__ b0,
                const float* __restrict__ W1,  const float* __restrict__ W2,
                const float* __restrict__ V0,  const float* __restrict__ c0,
                const float* __restrict__ V1,  const float* __restrict__ V2,
                const float* __restrict__ alpha,
                float* __restrict__ out)
{
    extern __shared__ float smem_raw[];
    Smem& sm = *reinterpret_cast<Smem*>(smem_raw);
    const int tid  = threadIdx.x;
    const int row0 = blockIdx.x * RT;

    // ================= Stage 1: norms (1 warp per row) =================
    {
        const int warp = tid >> 5, lane = tid & 31;
        const int r = warp;
        const float* xr = x + (size_t)(row0 + r) * D_IN;
        float vals[15];
        float sum0 = 0.f, sq0 = 0.f, sq12 = 0.f;
        #pragma unroll
        for (int k = 0; k < 15; ++k) {
            const int c = lane + 32 * k;
            const float v = xr[c];
            vals[k] = v;
            if (k < 4)       { sum0 += v; sq0 += v * v; }
            else if (k < 10) { sq12 += v * v * (0.5f / 192.0f); }
            else             { sq12 += v * v * (0.5f / 160.0f); }
        }
        #pragma unroll
        for (int o = 16; o > 0; o >>= 1) {
            sum0 += __shfl_xor_sync(0xffffffffu, sum0, o);
            sq0  += __shfl_xor_sync(0xffffffffu, sq0,  o);
            sq12 += __shfl_xor_sync(0xffffffffu, sq12, o);
        }
        const float mu    = sum0 * (1.0f / 128.0f);
        const float var   = sq0 * (1.0f / 128.0f) - mu * mu;
        const float is0   = rsqrtf(var + EPSF);
        const float inv12 = rsqrtf(sq12 + EPSF);
        #pragma unroll
        for (int k = 0; k < 15; ++k) {
            const int c = lane + 32 * k;
            const float v = vals[k];
            if (k < 4) {
                sm.y0[c * RT + r] = ((v - mu) * is0 * nw0[c] + nb0[c]) * INV_S0;
            } else if (k < 10) {
                const int cc = c - 128; const int u = cc / 3; const int m = cc - 3 * u;
                sm.y1[(m * NM1 + u) * RT + r] = v * inv12 * nw1[u] * INV_S1;
            } else {
                const int cc = c - 320; const int u = cc / 5; const int m = cc - 5 * u;
                sm.y2[(m * NM2 + u) * RT + r] = v * inv12 * nw2[u] * INV_S2;
            }
        }
    }
    __syncthreads();

    // ================= Stage 2a: H0 = Y0 @ W0 (+b0), activations ===========
    if (tid < 224) {
        const int j0 = tid * 4;
        u64t acc[4][RP];
        #pragma unroll
        for (int c = 0; c < 4; ++c)
            #pragma unroll
            for (int p = 0; p < RP; ++p) acc[c][p] = 0ull;

        float4 w = *(const float4*)(W0 + j0);
        for (int u = 0; u < NM0; ++u) {
            const int un = (u < NM0 - 1) ? u + 1 : u;
            const float4 wn = *(const float4*)(W0 + un * W0COLS + j0);
            const ulonglong2* yp = (const ulonglong2*)(sm.y0 + u * RT);
            const ulonglong2 ya = yp[0], yb = yp[1];
            u64t yv[RP] = {ya.x, ya.y, yb.x, yb.y};
            u64t wp[4]  = {pk2(w.x), pk2(w.y), pk2(w.z), pk2(w.w)};
            #pragma unroll
            for (int c = 0; c < 4; ++c)
                #pragma unroll
                for (int p = 0; p < RP; ++p) fm2(acc[c][p], yv[p], wp[c]);
            w = wn;
        }
        #pragma unroll
        for (int c = 0; c < 4; ++c) {
            const int col = j0 + c;
            const float bb = b0[col];
            float h[RT];
            #pragma unroll
            for (int p = 0; p < RP; ++p) {
                const float2 f = up2(acc[c][p]);
                h[2*p] = f.x + bb; h[2*p+1] = f.y + bb;
            }
            if (col < NH0) {
                #pragma unroll
                for (int q = 0; q < 2; ++q) {
                    float4 o;
                    o.x = h[4*q+0] * __fdividef(1.f, 1.f + __expf(-h[4*q+0])) * INV_T0;
                    o.y = h[4*q+1] * __fdividef(1.f, 1.f + __expf(-h[4*q+1])) * INV_T0;
                    o.z = h[4*q+2] * __fdividef(1.f, 1.f + __expf(-h[4*q+2])) * INV_T0;
                    o.w = h[4*q+3] * __fdividef(1.f, 1.f + __expf(-h[4*q+3])) * INV_T0;
                    ((float4*)(sm.s + col * RT))[q] = o;
                }
            } else {
                #pragma unroll
                for (int q = 0; q < 2; ++q) {
                    float4 o;
                    o.x = __fdividef(1.f, 1.f + __expf(-h[4*q+0]));
                    o.y = __fdividef(1.f, 1.f + __expf(-h[4*q+1]));
                    o.z = __fdividef(1.f, 1.f + __expf(-h[4*q+2]));
                    o.w = __fdividef(1.f, 1.f + __expf(-h[4*q+3]));
                    ((float4*)(sm.g + (col - NH0) * RT))[q] = o;
                }
            }
        }
    }
    __syncthreads();

    // ================= Stage 2b: h1 -> z1 (3 heads) ========================
    if (tid < 192) {
        const int m  = tid >> 6;
        const int j0 = (tid & 63) * 4;
        u64t acc[4][RP];
        #pragma unroll
        for (int c = 0; c < 4; ++c)
            #pragma unroll
            for (int p = 0; p < RP; ++p) acc[c][p] = 0ull;

        const float* yb0 = sm.y1 + (m * NM1) * RT;
        float4 w = *(const float4*)(W1 + j0);
        for (int u = 0; u < NM1; ++u) {
            const int un = (u < NM1 - 1) ? u + 1 : u;
            const float4 wn = *(const float4*)(W1 + un * NH1 + j0);
            const ulonglong2* yp = (const ulonglong2*)(yb0 + u * RT);
            const ulonglong2 ya = yp[0], yq = yp[1];
            u64t yv[RP] = {ya.x, ya.y, yq.x, yq.y};
            u64t wp[4]  = {pk2(w.x), pk2(w.y), pk2(w.z), pk2(w.w)};
            #pragma unroll
            for (int c = 0; c < 4; ++c)
                #pragma unroll
                for (int p = 0; p < RP; ++p) fm2(acc[c][p], yv[p], wp[c]);
            w = wn;
        }
        const u64t sc = pk2(INV_T1);
        #pragma unroll
        for (int c = 0; c < 4; ++c) {
            const int col = j0 + c;
            const ulonglong2* gp = (const ulonglong2*)(sm.g + col * RT);
            const ulonglong2 ga = gp[0], gb = gp[1];
            u64t gv[RP] = {ga.x, ga.y, gb.x, gb.y};
            ulonglong2* zp = (ulonglong2*)(sm.z1 + (m * NH1 + col) * RT);
            ulonglong2 z0, z1v;
            z0.x  = ml2(ml2(acc[c][0], gv[0]), sc);
            z0.y  = ml2(ml2(acc[c][1], gv[1]), sc);
            z1v.x = ml2(ml2(acc[c][2], gv[2]), sc);
            z1v.y = ml2(ml2(acc[c][3], gv[3]), sc);
            zp[0] = z0; zp[1] = z1v;
        }
    }

    // ================= Stage 2c: h2 -> z2 (5 heads) ========================
    if (tid >= 96) {
        const int t  = tid - 96;
        const int m  = t >> 5;
        const int j0 = (t & 31) * 4;
        u64t acc[4][RP];
        #pragma unroll
        for (int c = 0; c < 4; ++c)
            #pragma unroll
            for (int p = 0; p < RP; ++p) acc[c][p] = 0ull;

        const float* yb0 = sm.y2 + (m * NM2) * RT;
        float4 w = *(const float4*)(W2 + j0);
        for (int u = 0; u < NM2; ++u) {
            const int un = (u < NM2 - 1) ? u + 1 : u;
            const float4 wn = *(const float4*)(W2 + un * NH2 + j0);
            const ulonglong2* yp = (const ulonglong2*)(yb0 + u * RT);
            const ulonglong2 ya = yp[0], yq = yp[1];
            u64t yv[RP] = {ya.x, ya.y, yq.x, yq.y};
            u64t wp[4]  = {pk2(w.x), pk2(w.y), pk2(w.z), pk2(w.w)};
            #pragma unroll
            for (int c = 0; c < 4; ++c)
                #pragma unroll
                for (int p = 0; p < RP; ++p) fm2(acc[c][p], yv[p], wp[c]);
            w = wn;
        }
        const u64t sc = pk2(INV_T2);
        #pragma unroll
        for (int c = 0; c < 4; ++c) {
            const int col = j0 + c;
            const ulonglong2* gp = (const ulonglong2*)(sm.g + (NH1 + col) * RT);
            const ulonglong2 ga = gp[0], gb = gp[1];
            u64t gv[RP] = {ga.x, ga.y, gb.x, gb.y};
            ulonglong2* zp = (ulonglong2*)(sm.z2 + (m * NH2 + col) * RT);
            ulonglong2 z0, z1v;
            z0.x  = ml2(ml2(acc[c][0], gv[0]), sc);
            z0.y  = ml2(ml2(acc[c][1], gv[1]), sc);
            z1v.x = ml2(ml2(acc[c][2], gv[2]), sc);
            z1v.y = ml2(ml2(acc[c][3], gv[3]), sc);
            zp[0] = z0; zp[1] = z1v;
        }
    }
    __syncthreads();

    // ================= Stage 4a: o0 = s @ V0 (+c0), K-split by 2 ===========
    u64t acc0[RP];
    {
        const int j  = tid & 127;
        const int kh = tid >> 7;
        #pragma unroll
        for (int p = 0; p < RP; ++p) acc0[p] = 0ull;
        const int ub = kh * 256;
        for (int uu = 0; uu < 256; uu += 4) {
            const float w0_ = V0[(ub + uu + 0) * NM0 + j];
            const float w1_ = V0[(ub + uu + 1) * NM0 + j];
            const float w2_ = V0[(ub + uu + 2) * NM0 + j];
            const float w3_ = V0[(ub + uu + 3) * NM0 + j];
            #pragma unroll
            for (int q = 0; q < 4; ++q) {
                const float wsc = (q == 0) ? w0_ : (q == 1) ? w1_ : (q == 2) ? w2_ : w3_;
                const u64t wq = pk2(wsc);
                const ulonglong2* sp = (const ulonglong2*)(sm.s + (ub + uu + q) * RT);
                const ulonglong2 sa = sp[0], sb = sp[1];
                fm2(acc0[0], sa.x, wq); fm2(acc0[1], sa.y, wq);
                fm2(acc0[2], sb.x, wq); fm2(acc0[3], sb.y, wq);
            }
        }
        if (kh) {
            #pragma unroll
            for (int p = 0; p < RP; ++p) {
                const float2 f = up2(acc0[p]);
                sm.scratch[(2*p)   * NM0 + j] = f.x;
                sm.scratch[(2*p+1) * NM0 + j] = f.y;
            }
        }
    }
    __syncthreads();
    if (tid < 128) {
        const float cc = c0[tid];
        #pragma unroll
        for (int p = 0; p < RP; ++p) {
            const float2 f = up2(acc0[p]);
            sm.o0[(2*p)   * NM0 + tid] = f.x + sm.scratch[(2*p)   * NM0 + tid] + cc;
            sm.o0[(2*p+1) * NM0 + tid] = f.y + sm.scratch[(2*p+1) * NM0 + tid] + cc;
        }
    }

    // ================= Stage 4b: o1 = z1 @ V1 ==============================
    if (tid < 192) {
        const int m = tid >> 6;
        const int j = tid & 63;
        u64t acc[RP];
        #pragma unroll
        for (int p = 0; p < RP; ++p) acc[p] = 0ull;
        const float* zb = sm.z1 + (m * NH1) * RT;
        for (int u = 0; u < NH1; u += 4) {
            const float w0_ = V1[(u + 0) * NM1 + j];
            const float w1_ = V1[(u + 1) * NM1 + j];
            const float w2_ = V1[(u + 2) * NM1 + j];
            const float w3_ = V1[(u + 3) * NM1 + j];
            #pragma unroll
            for (int q = 0; q < 4; ++q) {
                const float wsc = (q == 0) ? w0_ : (q == 1) ? w1_ : (q == 2) ? w2_ : w3_;
                const u64t wq = pk2(wsc);
                const ulonglong2* sp = (const ulonglong2*)(zb + (u + q) * RT);
                const ulonglong2 sa = sp[0], sb = sp[1];
                fm2(acc[0], sa.x, wq); fm2(acc[1], sa.y, wq);
                fm2(acc[2], sb.x, wq); fm2(acc[3], sb.y, wq);
            }
        }
        #pragma unroll
        for (int p = 0; p < RP; ++p) {
            const float2 f = up2(acc[p]);
            sm.o1[(2*p)   * (3 * NM1) + m * NM1 + j] = f.x;
            sm.o1[(2*p+1) * (3 * NM1) + m * NM1 + j] = f.y;
        }
    }

    // ================= Stage 4c: o2 = z2 @ V2 ==============================
    if (tid >= 96) {
        const int t = tid - 96;
        const int m = t >> 5;
        const int j = t & 31;
        u64t acc[RP];
        #pragma unroll
        for (int p = 0; p < RP; ++p) acc[p] = 0ull;
        const float* zb = sm.z2 + (m * NH2) * RT;
        for (int u = 0; u < NH2; u += 4) {
            const float w0_ = V2[(u + 0) * NM2 + j];
            const float w1_ = V2[(u + 1) * NM2 + j];
            const float w2_ = V2[(u + 2) * NM2 + j];
            const float w3_ = V2[(u + 3) * NM2 + j];
            #pragma unroll
            for (int q = 0; q < 4; ++q) {
                const float wsc = (q == 0) ? w0_ : (q == 1) ? w1_ : (q == 2) ? w2_ : w3_;
                const u64t wq = pk2(wsc);
                const ulonglong2* sp = (const ulonglong2*)(zb + (u + q) * RT);
                const ulonglong2 sa = sp[0], sb = sp[1];
                fm2(acc[0], sa.x, wq); fm2(acc[1], sa.y, wq);
                fm2(acc[2], sb.x, wq); fm2(acc[3], sb.y, wq);
            }
        }
        #pragma unroll
        for (int p = 0; p < RP; ++p) {
            const float2 f = up2(acc[p]);
            sm.o2[(2*p)   * (5 * NM2) + m * NM2 + j] = f.x;
            sm.o2[(2*p+1) * (5 * NM2) + m * NM2 + j] = f.y;
        }
    }
    __syncthreads();

    // ================= Stage 5: out = x + tanh(alpha) * dx =================
    {
        const float t = tanhf(alpha[0]);
        #pragma unroll
        for (int i = tid; i < RT * D_IN; i += TPB) {
            const int r = i / D_IN;
            const int c = i - r * D_IN;
            float dx;
            if (c < 128) {
                dx = sm.o0[r * NM0 + c];
            } else if (c < 320) {
                const int cc = c - 128; const int u = cc / 3; const int m = cc - 3 * u;
                dx = sm.o1[r * (3 * NM1) + m * NM1 + u];
            } else {
                const int cc = c - 320; const int u = cc / 5; const int m = cc - 5 * u;
                dx = sm.o2[r * (5 * NM2) + m * NM2 + u];
            }
            const size_t idx = (size_t)(row0 + r) * D_IN + c;
            out[idx] = x[idx] + t * dx;
        }
    }
}

extern "C" void kernel_launch(void* const* d_in, const int* in_sizes, int n_in,
                              void* d_out, int out_size) {
    const float* x     = (const float*)d_in[0];
    const float* nw0   = (const float*)d_in[1];
    const float* nb0   = (const float*)d_in[2];
    const float* nw1   = (const float*)d_in[3];
    const float* nw2   = (const float*)d_in[4];
    const float* W0    = (const float*)d_in[5];
    const float* b0    = (const float*)d_in[6];
    const float* W1    = (const float*)d_in[7];
    const float* W2    = (const float*)d_in[8];
    const float* V0    = (const float*)d_in[9];
    const float* c0    = (const float*)d_in[10];
    const float* V1    = (const float*)d_in[11];
    const float* V2    = (const float*)d_in[12];
    const float* alpha = (const float*)d_in[13];
    float* out = (float*)d_out;

    const int n = in_sizes[0] / D_IN;
    const int grid = n / RT;

    cudaFuncSetAttribute(ffn_kernel, cudaFuncAttributeMaxDynamicSharedMemorySize,
                         (int)sizeof(Smem));
    ffn_kernel<<<grid, TPB, sizeof(Smem)>>>(x, nw0, nb0, nw1, nw2, W0, b0, W1, W2,
                                            V0, c0, V1, V2, alpha, out);
}